// round 15
// baseline (speedup 1.0000x reference)
#include <cuda_runtime.h>
#include <cuda_fp16.h>
#include <cstdint>

// CharEmb R13: pure-fp16 mma.sync im2col GEMM + fused max-pool (1 term).
//
// Precision calibration from R12: B-quantized-to-fp16 alone measured
// rel_err = 1.02e-4. Quantizing A too adds the same error in quadrature
// -> ~1.5e-4, still ~7x under the 1e-3 threshold. So drop the Al*Bh term:
// D = Ah*Bh only. HMMA count halves (384/block), A smem traffic halves.
//
// Semantics: x_w[e,c] = table[ids[w][e>>1]][(e&1)*32 + c]  (raw .view)
// out[w,f] = max_{t<30} sum_kk A[t,kk] B[kk,f] + bias[f];  kk = e*3+k.
// M=32 per word (rows 30,31 padded via c-clamp + masked), N=128, K=192.

#define NWORDS 16384
#define F_DIM  128
#define KSTEPS 12
#define SXS    33

typedef unsigned long long u64;

// B fragments (fp16): [ks][nt][lane] -> u64 = (b0, b1)
__device__ __align__(16) u64 g_Bfrag[KSTEPS * 16 * 32];   // 48 KB

__device__ __forceinline__ void mma_f16(float* d, const uint32_t* a,
                                        uint32_t b0, uint32_t b1) {
    asm volatile(
        "mma.sync.aligned.m16n8k16.row.col.f32.f16.f16.f32 "
        "{%0,%1,%2,%3}, {%4,%5,%6,%7}, {%8,%9}, {%0,%1,%2,%3};"
        : "+f"(d[0]), "+f"(d[1]), "+f"(d[2]), "+f"(d[3])
        : "r"(a[0]), "r"(a[1]), "r"(a[2]), "r"(a[3]), "r"(b0), "r"(b1));
}

__device__ __forceinline__ uint32_t pack_h2(float va, float vb) {
    __half2 h2 = __float22half2_rn(make_float2(va, vb));
    return *reinterpret_cast<uint32_t*>(&h2);
}

// ---------- prep: B fp16 fragments in mma layout ----------
__global__ __launch_bounds__(256) void prep_b_kernel(const float* __restrict__ w) {
    int idx = blockIdx.x * blockDim.x + threadIdx.x;
    if (idx >= KSTEPS * 16 * 32) return;
    int lane = idx & 31;
    int nt   = (idx >> 5) & 15;
    int ks   = idx >> 9;
    int tig = lane & 3, gid = lane >> 2;
    int f = nt * 8 + gid;

    uint32_t h[2];
    #pragma unroll
    for (int r = 0; r < 2; ++r) {
        int k0 = ks * 16 + 2 * tig + 8 * r;
        h[r] = pack_h2(w[f * 192 + k0], w[f * 192 + k0 + 1]);
    }
    g_Bfrag[(ks * 16 + nt) * 32 + lane] = ((u64)h[1] << 32) | h[0];
}

// ---------- main ----------
__global__ __launch_bounds__(128) void charemb_kernel(
    const int*   __restrict__ ids,     // [NWORDS, 32]
    const float* __restrict__ table,   // [101, 64]
    const float* __restrict__ bias,    // [128]
    float*       __restrict__ out)     // [NWORDS, 128]
{
    __shared__ float      sxf[64 * SXS];             // 8448 B
    __shared__ ulonglong2 sa[KSTEPS * 2 * 32];       // 12288 B: A fp16 fragments
    __shared__ float      red[F_DIM];

    const int n    = blockIdx.x;
    const int tid  = threadIdx.x;
    const int wid  = tid >> 5;
    const int lane = tid & 31;
    const int tig  = lane & 3;
    const int gid  = lane >> 2;

    // ---- gather x: sxf[e][c] = table[id[e>>1]][(e&1)*32 + c] ----
    const int* idn = ids + n * 32;
    #pragma unroll
    for (int j = 0; j < 16; ++j) {
        int p = tid + j * 128;
        int e = p >> 5, c = p & 31;
        sxf[e * SXS + c] = __ldg(table + __ldg(idn + (e >> 1)) * 64 + (e & 1) * 32 + c);
    }
    __syncthreads();

    // ---- build fp16 A fragments once: warp w -> ks = 3w..3w+2 ----
    #pragma unroll
    for (int i = 0; i < 3; ++i) {
        int ks  = wid * 3 + i;
        int kk0 = ks * 16 + 2 * tig;
        int e0 = kk0 / 3,       dk0 = kk0 - 3 * e0;
        int e1 = (kk0 + 1) / 3, dk1 = (kk0 + 1) - 3 * e1;
        int e8 = (kk0 + 8) / 3, dk8 = (kk0 + 8) - 3 * e8;
        int e9 = (kk0 + 9) / 3, dk9 = (kk0 + 9) - 3 * e9;

        #pragma unroll
        for (int mt = 0; mt < 2; ++mt) {
            int t0 = mt * 16 + gid;
            int t1 = t0 + 8;
            int c00 = min(t0 + dk0, 31), c01 = min(t0 + dk1, 31);
            int c10 = min(t1 + dk0, 31), c11 = min(t1 + dk1, 31);
            int c08 = min(t0 + dk8, 31), c09 = min(t0 + dk9, 31);
            int c18 = min(t1 + dk8, 31), c19 = min(t1 + dk9, 31);

            uint32_t a0 = pack_h2(sxf[e0 * SXS + c00], sxf[e1 * SXS + c01]);
            uint32_t a1 = pack_h2(sxf[e0 * SXS + c10], sxf[e1 * SXS + c11]);
            uint32_t a2 = pack_h2(sxf[e8 * SXS + c08], sxf[e9 * SXS + c09]);
            uint32_t a3 = pack_h2(sxf[e8 * SXS + c18], sxf[e9 * SXS + c19]);

            ulonglong2 v;
            v.x = ((u64)a1 << 32) | a0;
            v.y = ((u64)a3 << 32) | a2;
            sa[(ks * 2 + mt) * 32 + lane] = v;
        }
    }
    __syncthreads();

    // ---- MMA mainloop: LDG.64(B) + LDS.128(A) + HMMA ----
    float d[2][4][4];
    #pragma unroll
    for (int mt = 0; mt < 2; ++mt)
        #pragma unroll
        for (int l = 0; l < 4; ++l)
            #pragma unroll
            for (int r = 0; r < 4; ++r) d[mt][l][r] = 0.0f;

    #pragma unroll 4
    for (int ks = 0; ks < KSTEPS; ++ks) {
        u64 b[4];
        #pragma unroll
        for (int l = 0; l < 4; ++l)
            b[l] = __ldg(g_Bfrag + (ks * 16 + wid * 4 + l) * 32 + lane);

        #pragma unroll
        for (int mt = 0; mt < 2; ++mt) {
            ulonglong2 av = sa[(ks * 2 + mt) * 32 + lane];
            uint32_t a[4] = { (uint32_t)av.x, (uint32_t)(av.x >> 32),
                              (uint32_t)av.y, (uint32_t)(av.y >> 32) };
            #pragma unroll
            for (int l = 0; l < 4; ++l)
                mma_f16(d[mt][l], a, (uint32_t)b[l], (uint32_t)(b[l] >> 32));
        }
    }

    // ---- epilogue: max over t<30 ----
    #pragma unroll
    for (int l = 0; l < 4; ++l) {
        float ve = fmaxf(d[0][l][0], d[0][l][2]);
        float vo = fmaxf(d[0][l][1], d[0][l][3]);
        ve = fmaxf(ve, d[1][l][0]);
        vo = fmaxf(vo, d[1][l][1]);
        if (gid < 6) {
            ve = fmaxf(ve, d[1][l][2]);
            vo = fmaxf(vo, d[1][l][3]);
        }
        #pragma unroll
        for (int s = 4; s < 32; s <<= 1) {
            ve = fmaxf(ve, __shfl_xor_sync(0xffffffffu, ve, s));
            vo = fmaxf(vo, __shfl_xor_sync(0xffffffffu, vo, s));
        }
        if (gid == 0) {
            int f = (wid * 4 + l) * 8 + 2 * tig;
            red[f]     = ve;
            red[f + 1] = vo;
        }
    }
    __syncthreads();

    out[n * F_DIM + tid] = red[tid] + __ldg(bias + tid);
}

extern "C" void kernel_launch(void* const* d_in, const int* in_sizes, int n_in,
                              void* d_out, int out_size) {
    const int*   ids   = (const int*)  d_in[0];
    const float* table = (const float*)d_in[1];
    const float* w     = (const float*)d_in[2];
    const float* bias  = (const float*)d_in[3];
    float* out = (float*)d_out;

    prep_b_kernel<<<(KSTEPS * 16 * 32 + 255) / 256, 256>>>(w);
    charemb_kernel<<<NWORDS, 128>>>(ids, table, bias, out);
}

// round 16
// speedup vs baseline: 1.2808x; 1.2808x over previous
#include <cuda_runtime.h>
#include <cuda_fp16.h>
#include <cstdint>

// CharEmb R15: fp16 mma.sync im2col GEMM, K reordered as kk' = k*64 + e.
//
// With kk' ordering, each k-step (16 wide) has constant conv-shift k = ks>>2
// and contiguous e = (ks&3)*16 + [0,16). An mma A-fragment register is then
// two adjacent-e fp16 values of one x row -> a single LDS.32 from a
// transposed fp16 tile sxt[c][e]. This deletes R13's entire A-staging phase
// (scattered conflicted LDS + STS + cvt) which was ~40% of L1 wavefronts.
//
// sxt row stride = 41 words (82 halves): read banks (9*gid + tig + const)
// and write banks (9*lane + const) are all-distinct -> conflict-free.
// Rows c=32,33 zero-filled: no clamps; D rows 30,31 = 0, masked in epilogue.
//
// out[w,f] = max_{t<30} sum_kk A[t,kk] B[kk,f] + bias[f]
// x_w[e,c] = table[ids[w][e>>1]][(e&1)*32 + c]  (raw .view semantics)

#define NWORDS 16384
#define F_DIM  128
#define KSTEPS 12
#define SXW    41                 // sxt row stride in 32-bit words

typedef unsigned long long u64;

// B fragments (fp16, kk' order): [ks][nt][lane] -> u64 = (b0, b1)
__device__ __align__(16) u64 g_Bfrag[KSTEPS * 16 * 32];   // 48 KB

__device__ __forceinline__ void mma_f16(float* d, const uint32_t* a,
                                        uint32_t b0, uint32_t b1) {
    asm volatile(
        "mma.sync.aligned.m16n8k16.row.col.f32.f16.f16.f32 "
        "{%0,%1,%2,%3}, {%4,%5,%6,%7}, {%8,%9}, {%0,%1,%2,%3};"
        : "+f"(d[0]), "+f"(d[1]), "+f"(d[2]), "+f"(d[3])
        : "r"(a[0]), "r"(a[1]), "r"(a[2]), "r"(a[3]), "r"(b0), "r"(b1));
}

__device__ __forceinline__ uint32_t pack_h2(float va, float vb) {
    __half2 h2 = __float22half2_rn(make_float2(va, vb));
    return *reinterpret_cast<uint32_t*>(&h2);
}

// ---------- prep: B fp16 fragments, kk' = k*64 + e ordering ----------
__global__ __launch_bounds__(256) void prep_b_kernel(const float* __restrict__ w) {
    int idx = blockIdx.x * blockDim.x + threadIdx.x;
    if (idx >= KSTEPS * 16 * 32) return;
    int lane = idx & 31;
    int nt   = (idx >> 5) & 15;
    int ks   = idx >> 9;
    int tig = lane & 3, gid = lane >> 2;
    int f = nt * 8 + gid;
    int k = ks >> 2;

    uint32_t h[2];
    #pragma unroll
    for (int r = 0; r < 2; ++r) {
        int e = (ks & 3) * 16 + 2 * tig + 8 * r;
        h[r] = pack_h2(w[f * 192 + e * 3 + k],
                       w[f * 192 + (e + 1) * 3 + k]);
    }
    g_Bfrag[(ks * 16 + nt) * 32 + lane] = ((u64)h[1] << 32) | h[0];
}

// ---------- main ----------
__global__ __launch_bounds__(128) void charemb_kernel(
    const int*   __restrict__ ids,     // [NWORDS, 32]
    const float* __restrict__ table,   // [101, 64]
    const float* __restrict__ bias,    // [128]
    float*       __restrict__ out)     // [NWORDS, 128]
{
    // sxt[c][e]: word (c*41 + e/2) holds fp16 pair (x[e,c], x[e+1,c]).
    __shared__ uint32_t sxt[34 * SXW];           // 5576 B
    __shared__ float    red[F_DIM];

    const int n    = blockIdx.x;
    const int tid  = threadIdx.x;
    const int wid  = tid >> 5;
    const int lane = tid & 31;
    const int tig  = lane & 3;
    const int gid  = lane >> 2;

    // ---- gather: warp handles e-pair q = wid + 4j; lane = c.
    //      x[2q,c] = table[id[q]][c], x[2q+1,c] = table[id[q]][c+32]. ----
    const int* idn = ids + n * 32;
    #pragma unroll
    for (int j = 0; j < 8; ++j) {
        int q  = wid + 4 * j;
        int id = __ldg(idn + q);
        const float* row = table + id * 64;
        float lo = __ldg(row + lane);
        float hi = __ldg(row + 32 + lane);
        sxt[SXW * lane + q] = pack_h2(lo, hi);   // banks 9*lane+q: distinct
    }
    // zero pad rows c = 32, 33
    if (tid < 64) sxt[SXW * (32 + (tid >> 5)) + (tid & 31)] = 0;
    __syncthreads();

    // ---- MMA mainloop: 4 LDG.64(B) + 8 LDS.32(A) + 8 HMMA per ks ----
    float d[2][4][4];
    #pragma unroll
    for (int mt = 0; mt < 2; ++mt)
        #pragma unroll
        for (int l = 0; l < 4; ++l)
            #pragma unroll
            for (int r = 0; r < 4; ++r) d[mt][l][r] = 0.0f;

    const int abase = SXW * gid + tig;

    #pragma unroll 4
    for (int ks = 0; ks < KSTEPS; ++ks) {
        u64 b[4];
        #pragma unroll
        for (int l = 0; l < 4; ++l)
            b[l] = __ldg(g_Bfrag + (ks * 16 + wid * 4 + l) * 32 + lane);

        const int arow = abase + SXW * (ks >> 2) + 8 * (ks & 3);

        #pragma unroll
        for (int mt = 0; mt < 2; ++mt) {
            const int o = arow + SXW * 16 * mt;
            uint32_t a[4];
            a[0] = sxt[o];                  // row t0,   e' pair
            a[1] = sxt[o + SXW * 8];        // row t0+8, e' pair
            a[2] = sxt[o + 4];              // row t0,   e'+8 pair
            a[3] = sxt[o + SXW * 8 + 4];    // row t0+8, e'+8 pair
            #pragma unroll
            for (int l = 0; l < 4; ++l)
                mma_f16(d[mt][l], a, (uint32_t)b[l], (uint32_t)(b[l] >> 32));
        }
    }

    // ---- epilogue: max over t<30 (rows 30,31 are zero -> masked) ----
    #pragma unroll
    for (int l = 0; l < 4; ++l) {
        float ve = fmaxf(d[0][l][0], d[0][l][2]);
        float vo = fmaxf(d[0][l][1], d[0][l][3]);
        ve = fmaxf(ve, d[1][l][0]);
        vo = fmaxf(vo, d[1][l][1]);
        if (gid < 6) {
            ve = fmaxf(ve, d[1][l][2]);
            vo = fmaxf(vo, d[1][l][3]);
        }
        #pragma unroll
        for (int s = 4; s < 32; s <<= 1) {
            ve = fmaxf(ve, __shfl_xor_sync(0xffffffffu, ve, s));
            vo = fmaxf(vo, __shfl_xor_sync(0xffffffffu, vo, s));
        }
        if (gid == 0) {
            int f = (wid * 4 + l) * 8 + 2 * tig;
            red[f]     = ve;
            red[f + 1] = vo;
        }
    }
    __syncthreads();

    out[n * F_DIM + tid] = red[tid] + __ldg(bias + tid);
}

extern "C" void kernel_launch(void* const* d_in, const int* in_sizes, int n_in,
                              void* d_out, int out_size) {
    const int*   ids   = (const int*)  d_in[0];
    const float* table = (const float*)d_in[1];
    const float* w     = (const float*)d_in[2];
    const float* bias  = (const float*)d_in[3];
    float* out = (float*)d_out;

    prep_b_kernel<<<(KSTEPS * 16 * 32 + 255) / 256, 256>>>(w);
    charemb_kernel<<<NWORDS, 128>>>(ids, table, bias, out);
}

// round 17
// speedup vs baseline: 1.4497x; 1.1319x over previous
#include <cuda_runtime.h>
#include <cuda_fp16.h>
#include <cstdint>

// CharEmb R16: fp16 mma.sync im2col GEMM (kk' = k*64+e ordering), warp tile
// widened to 2 m-tiles x 8 n-tiles. Each warp now covers the full N=128 half
// per word -> 2 warps/word, 2 words per 128-thread block. L1 bytes/word drop
// 25% (B fragment reuse doubles: 16/b + 8/a : 8 -> 6 units).
//
// Carry-overs from R15: transposed fp16 x tile sxt[c][e2] with stride 41
// (conflict-free), zero-padded rows c=32,33 (no clamps, D rows 30,31 = 0,
// masked via gid<6), B fragments precomputed in mma layout (now paired as
// ulonglong2 for LDG.128).
//
// out[w,f] = max_{t<30} sum A B + bias[f];  x_w[e,c] = table[ids[w][e>>1]][(e&1)*32+c]

#define NWORDS 16384
#define WPB    2                   // words per block
#define F_DIM  128
#define KSTEPS 12
#define SXW    41                  // sxt row stride (words)
#define TILE_W (34 * SXW)          // words per x tile

typedef unsigned long long u64;

// B fragments paired: [ks][nh][lp][lane] -> ulonglong2 (nt = nh*8+2lp, +1)
__device__ __align__(16) u64 g_B2raw[KSTEPS * 2 * 4 * 32 * 2];   // 48 KB

__device__ __forceinline__ void mma_f16(float* d, const uint32_t* a,
                                        uint32_t b0, uint32_t b1) {
    asm volatile(
        "mma.sync.aligned.m16n8k16.row.col.f32.f16.f16.f32 "
        "{%0,%1,%2,%3}, {%4,%5,%6,%7}, {%8,%9}, {%0,%1,%2,%3};"
        : "+f"(d[0]), "+f"(d[1]), "+f"(d[2]), "+f"(d[3])
        : "r"(a[0]), "r"(a[1]), "r"(a[2]), "r"(a[3]), "r"(b0), "r"(b1));
}

__device__ __forceinline__ uint32_t pack_h2(float va, float vb) {
    __half2 h2 = __float22half2_rn(make_float2(va, vb));
    return *reinterpret_cast<uint32_t*>(&h2);
}

// ---------- prep: B fp16 fragments, kk' order, paired layout ----------
__global__ __launch_bounds__(256) void prep_b_kernel(const float* __restrict__ w) {
    int idx = blockIdx.x * blockDim.x + threadIdx.x;
    if (idx >= KSTEPS * 16 * 32) return;
    int lane = idx & 31;
    int nt   = (idx >> 5) & 15;
    int ks   = idx >> 9;
    int tig = lane & 3, gid = lane >> 2;
    int f = nt * 8 + gid;
    int k = ks >> 2;

    uint32_t h[2];
    #pragma unroll
    for (int r = 0; r < 2; ++r) {
        int e = (ks & 3) * 16 + 2 * tig + 8 * r;
        h[r] = pack_h2(w[f * 192 + e * 3 + k],
                       w[f * 192 + (e + 1) * 3 + k]);
    }
    u64 v = ((u64)h[1] << 32) | h[0];

    int nh = nt >> 3, l = nt & 7, lp = l >> 1, wh = l & 1;
    g_B2raw[(((ks * 2 + nh) * 4 + lp) * 32 + lane) * 2 + wh] = v;
}

// ---------- main ----------
__global__ __launch_bounds__(128) void charemb_kernel(
    const int*   __restrict__ ids,     // [NWORDS, 32]
    const float* __restrict__ table,   // [101, 64]
    const float* __restrict__ bias,    // [128]
    float*       __restrict__ out)     // [NWORDS, 128]
{
    __shared__ uint32_t sxt[WPB * TILE_W];       // 2 x 5576 B
    __shared__ float    red[WPB][F_DIM];

    const int n0   = blockIdx.x * WPB;
    const int tid  = threadIdx.x;
    const int wid  = tid >> 5;
    const int lane = tid & 31;
    const int tig  = lane & 3;
    const int gid  = lane >> 2;
    const int ww   = wid >> 1;        // word within block
    const int nh   = wid & 1;         // n-half (8 n-tiles)

    // ---- gather: warp pair (ww) fills word ww's tile; q = e-pair ----
    {
        const int* idn = ids + (n0 + ww) * 32;
        uint32_t* st = sxt + ww * TILE_W;
        #pragma unroll
        for (int j = 0; j < 16; ++j) {
            int q  = nh + 2 * j;
            int id = __ldg(idn + q);
            const float* row = table + id * 64;
            st[SXW * lane + q] = pack_h2(__ldg(row + lane), __ldg(row + 32 + lane));
        }
    }
    // zero pad rows c = 32, 33 of both tiles
    if (tid < 128) {
        int w2 = tid >> 6, r = 32 + ((tid >> 5) & 1), e2 = tid & 31;
        sxt[w2 * TILE_W + SXW * r + e2] = 0;
    }
    __syncthreads();

    // ---- MMA mainloop: 4 LDG.128(B) + 8 LDS.32(A) + 16 HMMA per ks ----
    float d[2][8][4];
    #pragma unroll
    for (int mt = 0; mt < 2; ++mt)
        #pragma unroll
        for (int l = 0; l < 8; ++l)
            #pragma unroll
            for (int r = 0; r < 4; ++r) d[mt][l][r] = 0.0f;

    const ulonglong2* g_B2 = reinterpret_cast<const ulonglong2*>(g_B2raw);
    const int abase = ww * TILE_W + SXW * gid + tig;

    #pragma unroll 3
    for (int ks = 0; ks < KSTEPS; ++ks) {
        ulonglong2 bb[4];
        #pragma unroll
        for (int lp = 0; lp < 4; ++lp)
            bb[lp] = __ldg(g_B2 + ((ks * 2 + nh) * 4 + lp) * 32 + lane);

        const int arow = abase + SXW * (ks >> 2) + 8 * (ks & 3);

        #pragma unroll
        for (int mt = 0; mt < 2; ++mt) {
            const int o = arow + SXW * 16 * mt;
            uint32_t a[4];
            a[0] = sxt[o];
            a[1] = sxt[o + SXW * 8];
            a[2] = sxt[o + 4];
            a[3] = sxt[o + SXW * 8 + 4];
            #pragma unroll
            for (int l = 0; l < 8; ++l) {
                u64 bv = (l & 1) ? bb[l >> 1].y : bb[l >> 1].x;
                mma_f16(d[mt][l], a, (uint32_t)bv, (uint32_t)(bv >> 32));
            }
        }
    }

    // ---- epilogue: max over t<30 (rows 30,31 zero -> masked via gid<6) ----
    #pragma unroll
    for (int l = 0; l < 8; ++l) {
        float ve = fmaxf(d[0][l][0], d[0][l][2]);
        float vo = fmaxf(d[0][l][1], d[0][l][3]);
        ve = fmaxf(ve, d[1][l][0]);
        vo = fmaxf(vo, d[1][l][1]);
        if (gid < 6) {
            ve = fmaxf(ve, d[1][l][2]);
            vo = fmaxf(vo, d[1][l][3]);
        }
        #pragma unroll
        for (int s = 4; s < 32; s <<= 1) {
            ve = fmaxf(ve, __shfl_xor_sync(0xffffffffu, ve, s));
            vo = fmaxf(vo, __shfl_xor_sync(0xffffffffu, vo, s));
        }
        if (gid == 0) {
            int f = (nh * 8 + l) * 8 + 2 * tig;
            red[ww][f]     = ve;
            red[ww][f + 1] = vo;
        }
    }
    __syncthreads();

    #pragma unroll
    for (int r = 0; r < WPB; ++r)
        out[(n0 + r) * F_DIM + tid] = red[r][tid] + __ldg(bias + tid);
}

extern "C" void kernel_launch(void* const* d_in, const int* in_sizes, int n_in,
                              void* d_out, int out_size) {
    const int*   ids   = (const int*)  d_in[0];
    const float* table = (const float*)d_in[1];
    const float* w     = (const float*)d_in[2];
    const float* bias  = (const float*)d_in[3];
    float* out = (float*)d_out;

    prep_b_kernel<<<(KSTEPS * 16 * 32 + 255) / 256, 256>>>(w);
    charemb_kernel<<<NWORDS / WPB, 128>>>(ids, table, bias, out);
}